// round 3
// baseline (speedup 1.0000x reference)
#include <cuda_runtime.h>
#include <math.h>

#define BATCH   2
#define SEQ     2048
#define DMODEL  1024
#define NHEAD   16
#define DK      64
#define BHTOT   (BATCH*NHEAD)     // 32
#define NEGBIG  -1e8f

// ---------------- scratch (static device globals; no allocation) -------------
__device__ float g_Q[BHTOT*SEQ*DK];   // [b,h,s,dk]
__device__ float g_K[BHTOT*SEQ*DK];
__device__ float g_V[BHTOT*SEQ*DK];
__device__ float g_bias[BATCH*SEQ];   // 0 or -1e8 per key position
__device__ int   g_maskmode;          // 1 = byte mask, 0 = int32 mask

// ---------------- helpers ----------------------------------------------------
__device__ __forceinline__ unsigned f2tf(float f) {
    unsigned u;
    asm("cvt.rna.tf32.f32 %0, %1;" : "=r"(u) : "f"(f));
    return u;
}

__device__ __forceinline__ void mma_tf32(float c[4],
    unsigned a0, unsigned a1, unsigned a2, unsigned a3,
    unsigned b0, unsigned b1)
{
    asm volatile(
        "mma.sync.aligned.m16n8k8.row.col.f32.tf32.tf32.f32 "
        "{%0,%1,%2,%3}, {%4,%5,%6,%7}, {%8,%9}, {%0,%1,%2,%3};"
        : "+f"(c[0]), "+f"(c[1]), "+f"(c[2]), "+f"(c[3])
        : "r"(a0), "r"(a1), "r"(a2), "r"(a3), "r"(b0), "r"(b1));
}

// ---------------- mask dtype detection + bias build ---------------------------
__global__ void detect_mask_kernel(const unsigned int* __restrict__ m) {
    __shared__ int flag;
    if (threadIdx.x == 0) flag = 0;
    __syncthreads();
    for (int i = threadIdx.x; i < 1024; i += blockDim.x) {
        if (m[i] & 0xFFFFFF00u) flag = 1;
    }
    __syncthreads();
    if (threadIdx.x == 0) g_maskmode = flag;
}

__global__ void build_bias_kernel(const void* __restrict__ mask) {
    int i = blockIdx.x * blockDim.x + threadIdx.x;
    if (i >= BATCH * SEQ) return;
    bool masked;
    if (g_maskmode) masked = ((const unsigned char*)mask)[i] != 0;
    else            masked = ((const int*)mask)[i] != 0;
    g_bias[i] = masked ? NEGBIG : 0.0f;
}

// ---------------- QKV projection (tf32 tensor cores) --------------------------
// out = X @ W^T + b, scattered to [b,h,s,dk].
// Tile 128x128x32, 8 warps, warp tile 32x64. Both X and W are K-contiguous:
// natural [row][k] smem layout works for A and B fragments of .row.col mma.
__global__ __launch_bounds__(256) void qkv_gemm_tc(
    const float* __restrict__ X, const float* __restrict__ W,
    const float* __restrict__ bias, float* __restrict__ out)
{
    __shared__ unsigned As[128][36];   // pad 36: frag LDS conflict-free, 144B rows (16B aligned)
    __shared__ unsigned Ws[128][36];

    const int tid  = threadIdx.x;
    const int warp = tid >> 5, lane = tid & 31;
    const int lr   = lane >> 2, qq = lane & 3;
    const int wr   = warp >> 1;          // 0..3 -> m offset wr*32
    const int wc   = warp & 1;           // 0..1 -> n offset wc*64
    const int m0   = blockIdx.y * 128;
    const int n0   = blockIdx.x * 128;

    const int trow = tid >> 3;           // 0..31
    const int tkq  = tid & 7;            // 0..7

    float acc[2][8][4];
    #pragma unroll
    for (int mt = 0; mt < 2; mt++)
        #pragma unroll
        for (int nt = 0; nt < 8; nt++)
            #pragma unroll
            for (int e = 0; e < 4; e++) acc[mt][nt][e] = 0.0f;

    float4 ra[4], rw[4];
    #pragma unroll
    for (int i = 0; i < 4; i++) {
        ra[i] = *(const float4*)&X[(size_t)(m0 + trow + 32*i) * DMODEL + tkq*4];
        rw[i] = *(const float4*)&W[(size_t)(n0 + trow + 32*i) * DMODEL + tkq*4];
    }

    for (int k0 = 0; k0 < DMODEL; k0 += 32) {
        __syncthreads();
        #pragma unroll
        for (int i = 0; i < 4; i++) {
            uint4 ua = make_uint4(f2tf(ra[i].x), f2tf(ra[i].y), f2tf(ra[i].z), f2tf(ra[i].w));
            *(uint4*)&As[trow + 32*i][tkq*4] = ua;
            uint4 uw = make_uint4(f2tf(rw[i].x), f2tf(rw[i].y), f2tf(rw[i].z), f2tf(rw[i].w));
            *(uint4*)&Ws[trow + 32*i][tkq*4] = uw;
        }
        __syncthreads();
        if (k0 + 32 < DMODEL) {
            #pragma unroll
            for (int i = 0; i < 4; i++) {
                ra[i] = *(const float4*)&X[(size_t)(m0 + trow + 32*i)*DMODEL + k0 + 32 + tkq*4];
                rw[i] = *(const float4*)&W[(size_t)(n0 + trow + 32*i)*DMODEL + k0 + 32 + tkq*4];
            }
        }
        #pragma unroll
        for (int ks = 0; ks < 4; ks++) {
            const int kb = ks * 8;
            unsigned a[2][4];
            #pragma unroll
            for (int mt = 0; mt < 2; mt++) {
                int r = wr*32 + mt*16 + lr;
                a[mt][0] = As[r    ][kb + qq];
                a[mt][1] = As[r + 8][kb + qq];
                a[mt][2] = As[r    ][kb + qq + 4];
                a[mt][3] = As[r + 8][kb + qq + 4];
            }
            #pragma unroll
            for (int nt = 0; nt < 8; nt++) {
                int c = wc*64 + nt*8 + lr;
                unsigned b0 = Ws[c][kb + qq];
                unsigned b1 = Ws[c][kb + qq + 4];
                mma_tf32(acc[0][nt], a[0][0], a[0][1], a[0][2], a[0][3], b0, b1);
                mma_tf32(acc[1][nt], a[1][0], a[1][1], a[1][2], a[1][3], b0, b1);
            }
        }
    }

    // epilogue: scatter to [b,h,s,dk] with bias
    #pragma unroll
    for (int mt = 0; mt < 2; mt++) {
        #pragma unroll
        for (int er = 0; er < 2; er++) {
            int m  = m0 + wr*32 + mt*16 + lr + er*8;
            int bb = m >> 11;
            int s  = m & (SEQ - 1);
            #pragma unroll
            for (int nt = 0; nt < 8; nt++) {
                int n = n0 + wc*64 + nt*8 + 2*qq;
                int h = n >> 6;
                int d = n & (DK - 1);
                float2 v;
                v.x = acc[mt][nt][er*2 + 0] + bias[n];
                v.y = acc[mt][nt][er*2 + 1] + bias[n + 1];
                *(float2*)&out[((size_t)(bb*NHEAD + h)*SEQ + s)*DK + d] = v;
            }
        }
    }
}

// ---------------- fused flash attention (tf32 tensor cores) -------------------
// CTA: 256 threads (8 warps), 128 query rows (16 per warp). 64-key tiles.
// S and O live in mma accumulators; P round-trips through per-warp smem.
#define QT   128
#define PQS  68    // Qs/Ps pad: frag bank = 4*(lane>>2)+lane%4 unique; 272B rows
#define PKS  68    // Ks pad (same fragment pattern as Q)
#define PVS  72    // Vs pad: frag bank = 8*(lane%4)+(lane>>2) unique; 288B rows

__global__ __launch_bounds__(256) void attn_tc_kernel(float* __restrict__ out) {
    extern __shared__ unsigned sm[];
    unsigned* Qs = sm;                        // QT * PQS   = 8704
    unsigned* Ks = Qs + QT*PQS;               // 64 * PKS   = 4352
    unsigned* Vs = Ks + 64*PKS;               // 64 * PVS   = 4608
    unsigned* Ps = Vs + 64*PVS;               // QT * PQS   = 8704
    float*    bs = (float*)(Ps + QT*PQS);     // 64

    const int tid  = threadIdx.x;
    const int warp = tid >> 5, lane = tid & 31;
    const int lr   = lane >> 2, qq = lane & 3;
    const int wrow = warp * 16;               // this warp's 16 q rows (local)

    const int bh = blockIdx.y;                // 0..31
    const int q0 = blockIdx.x * QT;
    const float* Qb = g_Q + ((size_t)bh*SEQ + q0) * DK;
    const float* Kb = g_K + (size_t)bh*SEQ*DK;
    const float* Vb = g_V + (size_t)bh*SEQ*DK;
    const int bias_base = (bh >> 4) * SEQ;    // b*SEQ

    // load Q tile (128x64) as tf32, natural [r][d] layout
    #pragma unroll
    for (int i = 0; i < 8; i++) {
        int t = tid + i*256;                  // 2048 float4 tasks
        int r = t >> 4, dq = t & 15;
        float4 v = *(const float4*)&Qb[(size_t)r*DK + 4*dq];
        uint4 u = make_uint4(f2tf(v.x), f2tf(v.y), f2tf(v.z), f2tf(v.w));
        *(uint4*)&Qs[r*PQS + 4*dq] = u;
    }

    float S[8][4], O[8][4];
    float mrow[2] = {-INFINITY, -INFINITY};
    float lrow[2] = {0.0f, 0.0f};
    #pragma unroll
    for (int nt = 0; nt < 8; nt++)
        #pragma unroll
        for (int e = 0; e < 4; e++) O[nt][e] = 0.0f;

    for (int t = 0; t < SEQ/64; t++) {
        __syncthreads();   // prior-iteration mma reads done before K/V overwrite
        #pragma unroll
        for (int i = 0; i < 4; i++) {
            int tk = tid + i*256;             // 1024 float4 tasks each for K,V
            int c = tk >> 4, dq = tk & 15;
            float4 kv = *(const float4*)&Kb[(size_t)(t*64 + c)*DK + 4*dq];
            *(uint4*)&Ks[c*PKS + 4*dq] =
                make_uint4(f2tf(kv.x), f2tf(kv.y), f2tf(kv.z), f2tf(kv.w));
            float4 vv = *(const float4*)&Vb[(size_t)(t*64 + c)*DK + 4*dq];
            *(uint4*)&Vs[c*PVS + 4*dq] =
                make_uint4(f2tf(vv.x), f2tf(vv.y), f2tf(vv.z), f2tf(vv.w));
        }
        if (tid < 64) bs[tid] = g_bias[bias_base + t*64 + tid];
        __syncthreads();

        // ---- S = Q K^T ----
        #pragma unroll
        for (int nt = 0; nt < 8; nt++)
            #pragma unroll
            for (int e = 0; e < 4; e++) S[nt][e] = 0.0f;
        #pragma unroll
        for (int ks = 0; ks < 8; ks++) {
            const int kb = ks * 8;
            unsigned a0 = Qs[(wrow + lr    )*PQS + kb + qq];
            unsigned a1 = Qs[(wrow + lr + 8)*PQS + kb + qq];
            unsigned a2 = Qs[(wrow + lr    )*PQS + kb + qq + 4];
            unsigned a3 = Qs[(wrow + lr + 8)*PQS + kb + qq + 4];
            #pragma unroll
            for (int nt = 0; nt < 8; nt++) {
                unsigned b0 = Ks[(nt*8 + lr)*PKS + kb + qq];
                unsigned b1 = Ks[(nt*8 + lr)*PKS + kb + qq + 4];
                mma_tf32(S[nt], a0, a1, a2, a3, b0, b1);
            }
        }

        // ---- online softmax ----
        const float inv = 0.125f;   // 1/sqrt(64)
        float tm[2] = {-INFINITY, -INFINITY};
        #pragma unroll
        for (int nt = 0; nt < 8; nt++) {
            float b0 = bs[nt*8 + 2*qq];
            float b1 = bs[nt*8 + 2*qq + 1];
            S[nt][0] = S[nt][0]*inv + b0;  S[nt][1] = S[nt][1]*inv + b1;
            S[nt][2] = S[nt][2]*inv + b0;  S[nt][3] = S[nt][3]*inv + b1;
            tm[0] = fmaxf(tm[0], fmaxf(S[nt][0], S[nt][1]));
            tm[1] = fmaxf(tm[1], fmaxf(S[nt][2], S[nt][3]));
        }
        #pragma unroll
        for (int r = 0; r < 2; r++) {
            tm[r] = fmaxf(tm[r], __shfl_xor_sync(0xffffffffu, tm[r], 1));
            tm[r] = fmaxf(tm[r], __shfl_xor_sync(0xffffffffu, tm[r], 2));
        }
        float alpha[2], tl[2];
        #pragma unroll
        for (int r = 0; r < 2; r++) {
            float mn = fmaxf(mrow[r], tm[r]);
            alpha[r] = __expf(mrow[r] - mn);
            mrow[r] = mn;
            tl[r] = 0.0f;
            #pragma unroll
            for (int nt = 0; nt < 8; nt++) {
                float p0 = __expf(S[nt][2*r + 0] - mn);
                float p1 = __expf(S[nt][2*r + 1] - mn);
                S[nt][2*r + 0] = p0;  S[nt][2*r + 1] = p1;
                tl[r] += p0 + p1;
            }
            tl[r] += __shfl_xor_sync(0xffffffffu, tl[r], 1);
            tl[r] += __shfl_xor_sync(0xffffffffu, tl[r], 2);
            lrow[r] = lrow[r]*alpha[r] + tl[r];
            #pragma unroll
            for (int nt = 0; nt < 8; nt++) {
                O[nt][2*r + 0] *= alpha[r];
                O[nt][2*r + 1] *= alpha[r];
            }
        }

        // ---- write P (per-warp private region; only warp-level ordering needed) ----
        #pragma unroll
        for (int nt = 0; nt < 8; nt++) {
            Ps[(wrow + lr    )*PQS + nt*8 + 2*qq    ] = f2tf(S[nt][0]);
            Ps[(wrow + lr    )*PQS + nt*8 + 2*qq + 1] = f2tf(S[nt][1]);
            Ps[(wrow + lr + 8)*PQS + nt*8 + 2*qq    ] = f2tf(S[nt][2]);
            Ps[(wrow + lr + 8)*PQS + nt*8 + 2*qq + 1] = f2tf(S[nt][3]);
        }
        __syncwarp();

        // ---- O += P V ----
        #pragma unroll
        for (int ks = 0; ks < 8; ks++) {
            const int kb = ks * 8;
            unsigned a0 = Ps[(wrow + lr    )*PQS + kb + qq];
            unsigned a1 = Ps[(wrow + lr + 8)*PQS + kb + qq];
            unsigned a2 = Ps[(wrow + lr    )*PQS + kb + qq + 4];
            unsigned a3 = Ps[(wrow + lr + 8)*PQS + kb + qq + 4];
            #pragma unroll
            for (int nt = 0; nt < 8; nt++) {
                unsigned b0 = Vs[(kb + qq    )*PVS + nt*8 + lr];
                unsigned b1 = Vs[(kb + qq + 4)*PVS + nt*8 + lr];
                mma_tf32(O[nt], a0, a1, a2, a3, b0, b1);
            }
        }
        __syncwarp();   // PV reads of Ps done before next-iteration overwrite
    }

    // ---- epilogue: out[b, q, h*DK + d] ----
    const int b = bh >> 4, h = bh & (NHEAD - 1);
    #pragma unroll
    for (int r = 0; r < 2; r++) {
        float invl = 1.0f / lrow[r];
        int qrow = q0 + wrow + lr + r*8;
        size_t base = ((size_t)b*SEQ + qrow)*DMODEL + h*DK;
        #pragma unroll
        for (int nt = 0; nt < 8; nt++) {
            float2 v;
            v.x = O[nt][2*r + 0] * invl;
            v.y = O[nt][2*r + 1] * invl;
            *(float2*)&out[base + nt*8 + 2*qq] = v;
        }
    }
}

// ---------------- launch -----------------------------------------------------
extern "C" void kernel_launch(void* const* d_in, const int* in_sizes, int n_in,
                              void* d_out, int out_size)
{
    const float* input = (const float*)d_in[0];
    const void*  mask  = d_in[1];
    const float* Wq    = (const float*)d_in[2];
    const float* bq    = (const float*)d_in[3];
    const float* Wk    = (const float*)d_in[4];
    const float* bk    = (const float*)d_in[5];
    const float* Wv    = (const float*)d_in[6];
    const float* bv    = (const float*)d_in[7];
    float* out = (float*)d_out;

    float *qp, *kp, *vp;
    cudaGetSymbolAddress((void**)&qp, g_Q);
    cudaGetSymbolAddress((void**)&kp, g_K);
    cudaGetSymbolAddress((void**)&vp, g_V);

    detect_mask_kernel<<<1, 256>>>((const unsigned int*)mask);
    build_bias_kernel<<<(BATCH*SEQ + 255)/256, 256>>>(mask);

    dim3 ggrid(DMODEL/128, (BATCH*SEQ)/128);   // (8, 32)
    qkv_gemm_tc<<<ggrid, 256>>>(input, Wq, bq, qp);
    qkv_gemm_tc<<<ggrid, 256>>>(input, Wk, bk, kp);
    qkv_gemm_tc<<<ggrid, 256>>>(input, Wv, bv, vp);

    static int attn_smem_set = 0;
    const int smem_bytes = (QT*PQS + 64*PKS + 64*PVS + QT*PQS + 64) * sizeof(unsigned);
    if (!attn_smem_set) {
        cudaFuncSetAttribute(attn_tc_kernel,
                             cudaFuncAttributeMaxDynamicSharedMemorySize,
                             smem_bytes);
        attn_smem_set = 1;
    }
    dim3 agrid(SEQ/QT, BHTOT);                 // (16, 32)
    attn_tc_kernel<<<agrid, 256, smem_bytes>>>(out);
}

// round 4
// speedup vs baseline: 1.2965x; 1.2965x over previous
#include <cuda_runtime.h>
#include <cuda_fp16.h>
#include <math.h>

#define BATCH   2
#define SEQ     2048
#define DMODEL  1024
#define NHEAD   16
#define DK      64
#define BHTOT   (BATCH*NHEAD)     // 32
#define NEGBIG  -1e8f

// ---------------- scratch (static device globals; no allocation) -------------
__device__ __half g_Qh[BHTOT*SEQ*DK];    // [b,h,s,d]
__device__ __half g_Kh[BHTOT*SEQ*DK];    // [b,h,s,d]
__device__ __half g_Vth[BHTOT*DK*SEQ];   // [b,h,d,s]  (transposed V)
__device__ float  g_bias[BATCH*SEQ];     // 0 or -1e8 per key position
__device__ int    g_maskmode;            // 1 = byte mask, 0 = int32 mask

// ---------------- helpers ----------------------------------------------------
__device__ __forceinline__ unsigned pack2h(float x, float y) {
    __half2 h = __floats2half2_rn(x, y);
    return *(unsigned*)&h;
}

__device__ __forceinline__ void mma_f16(float c[4],
    unsigned a0, unsigned a1, unsigned a2, unsigned a3,
    unsigned b0, unsigned b1)
{
    asm volatile(
        "mma.sync.aligned.m16n8k16.row.col.f32.f16.f16.f32 "
        "{%0,%1,%2,%3}, {%4,%5,%6,%7}, {%8,%9}, {%0,%1,%2,%3};"
        : "+f"(c[0]), "+f"(c[1]), "+f"(c[2]), "+f"(c[3])
        : "r"(a0), "r"(a1), "r"(a2), "r"(a3), "r"(b0), "r"(b1));
}

__device__ __forceinline__ uint4 cvt8(const float* p) {
    float4 f0 = *(const float4*)(p);
    float4 f1 = *(const float4*)(p + 4);
    return make_uint4(pack2h(f0.x,f0.y), pack2h(f0.z,f0.w),
                      pack2h(f1.x,f1.y), pack2h(f1.z,f1.w));
}

// ---------------- mask dtype detection + bias build ---------------------------
__global__ void detect_mask_kernel(const unsigned int* __restrict__ m) {
    __shared__ int flag;
    if (threadIdx.x == 0) flag = 0;
    __syncthreads();
    for (int i = threadIdx.x; i < 1024; i += blockDim.x) {
        if (m[i] & 0xFFFFFF00u) flag = 1;
    }
    __syncthreads();
    if (threadIdx.x == 0) g_maskmode = flag;
}

__global__ void build_bias_kernel(const void* __restrict__ mask) {
    int i = blockIdx.x * blockDim.x + threadIdx.x;
    if (i >= BATCH * SEQ) return;
    bool masked;
    if (g_maskmode) masked = ((const unsigned char*)mask)[i] != 0;
    else            masked = ((const int*)mask)[i] != 0;
    g_bias[i] = masked ? NEGBIG : 0.0f;
}

// ---------------- fused QKV projection (fp16 tensor cores) --------------------
// gridDim.z selects Q/K/V. out = X @ W^T + b.
// Q,K scattered to [b,h,s,d] half; V scattered TRANSPOSED to [b,h,d,s] half.
#define GP 40   // smem row pitch (halfs): frag banks 20*row+qq distinct; STS conflict-free

__global__ __launch_bounds__(256) void qkv3_gemm_f16(
    const float* __restrict__ X,
    const float* __restrict__ W0, const float* __restrict__ W1, const float* __restrict__ W2,
    const float* __restrict__ b0p, const float* __restrict__ b1p, const float* __restrict__ b2p,
    __half* __restrict__ o0, __half* __restrict__ o1, __half* __restrict__ o2)
{
    const int z = blockIdx.z;
    const float* W    = (z == 0) ? W0 : (z == 1) ? W1 : W2;
    const float* bias = (z == 0) ? b0p : (z == 1) ? b1p : b2p;
    __half* out       = (z == 0) ? o0 : (z == 1) ? o1 : o2;

    __shared__ __half As[128][GP];
    __shared__ __half Ws[128][GP];

    const int tid  = threadIdx.x;
    const int warp = tid >> 5, lane = tid & 31;
    const int lr   = lane >> 2, qq = lane & 3;
    const int wr   = warp >> 1;          // m offset wr*32
    const int wc   = warp & 1;           // n offset wc*64
    const int m0   = blockIdx.y * 128;
    const int n0   = blockIdx.x * 128;

    const int row  = tid & 127;          // 0..127
    const int koff = (tid >> 7) * 16;    // 0 or 16 (halfs)

    float acc[2][8][4];
    #pragma unroll
    for (int mt = 0; mt < 2; mt++)
        #pragma unroll
        for (int nt = 0; nt < 8; nt++)
            #pragma unroll
            for (int e = 0; e < 4; e++) acc[mt][nt][e] = 0.0f;

    const float* Xp = X + (size_t)(m0 + row) * DMODEL + koff;
    const float* Wp = W + (size_t)(n0 + row) * DMODEL + koff;

    uint4 pA0 = cvt8(Xp),     pA1 = cvt8(Xp + 8);
    uint4 pW0 = cvt8(Wp),     pW1 = cvt8(Wp + 8);

    for (int k0 = 0; k0 < DMODEL; k0 += 32) {
        __syncthreads();
        *(uint4*)&As[row][koff]     = pA0;
        *(uint4*)&As[row][koff + 8] = pA1;
        *(uint4*)&Ws[row][koff]     = pW0;
        *(uint4*)&Ws[row][koff + 8] = pW1;
        __syncthreads();
        if (k0 + 32 < DMODEL) {
            pA0 = cvt8(Xp + k0 + 32);  pA1 = cvt8(Xp + k0 + 40);
            pW0 = cvt8(Wp + k0 + 32);  pW1 = cvt8(Wp + k0 + 40);
        }
        #pragma unroll
        for (int ks = 0; ks < 2; ks++) {
            const int kb = ks * 16;
            unsigned a[2][4];
            #pragma unroll
            for (int mt = 0; mt < 2; mt++) {
                int r = wr*32 + mt*16 + lr;
                a[mt][0] = *(const unsigned*)&As[r    ][kb + 2*qq];
                a[mt][1] = *(const unsigned*)&As[r + 8][kb + 2*qq];
                a[mt][2] = *(const unsigned*)&As[r    ][kb + 2*qq + 8];
                a[mt][3] = *(const unsigned*)&As[r + 8][kb + 2*qq + 8];
            }
            #pragma unroll
            for (int nt = 0; nt < 8; nt++) {
                int c = wc*64 + nt*8 + lr;
                unsigned bb0 = *(const unsigned*)&Ws[c][kb + 2*qq];
                unsigned bb1 = *(const unsigned*)&Ws[c][kb + 2*qq + 8];
                mma_f16(acc[0][nt], a[0][0], a[0][1], a[0][2], a[0][3], bb0, bb1);
                mma_f16(acc[1][nt], a[1][0], a[1][1], a[1][2], a[1][3], bb0, bb1);
            }
        }
    }

    #pragma unroll
    for (int mt = 0; mt < 2; mt++) {
        #pragma unroll
        for (int er = 0; er < 2; er++) {
            int m  = m0 + wr*32 + mt*16 + lr + er*8;
            int bb = m >> 11;             // batch
            int s  = m & (SEQ - 1);
            #pragma unroll
            for (int nt = 0; nt < 8; nt++) {
                int n = n0 + wc*64 + nt*8 + 2*qq;
                int h = n >> 6;
                int d = n & (DK - 1);
                float v0 = acc[mt][nt][er*2 + 0] + bias[n];
                float v1 = acc[mt][nt][er*2 + 1] + bias[n + 1];
                if (z != 2) {
                    __half2 hv = __floats2half2_rn(v0, v1);
                    *(__half2*)&out[((size_t)(bb*NHEAD + h)*SEQ + s)*DK + d] = hv;
                } else {
                    size_t base = ((size_t)(bb*NHEAD + h)*DK + d)*SEQ + s;
                    out[base]             = __float2half_rn(v0);
                    out[base + SEQ]       = __float2half_rn(v1);
                }
            }
        }
    }
}

// ---------------- fused flash attention (fp16 tensor cores) -------------------
#define QT  128
#define AP  72   // smem row pitch (halfs): frag banks 4*row+qq distinct

__global__ __launch_bounds__(256, 2) void attn_f16_kernel(float* __restrict__ out) {
    extern __shared__ char smraw[];
    float*  sbias = (float*)smraw;                      // SEQ floats = 8 KB
    __half* Qs = (__half*)(smraw + SEQ*sizeof(float));  // 128 x AP
    __half* Ks = Qs + QT*AP;                            // 64 x AP
    __half* Vt = Ks + 64*AP;                            // 64 x AP (rows = d)

    const int tid  = threadIdx.x;
    const int warp = tid >> 5, lane = tid & 31;
    const int lr   = lane >> 2, qq = lane & 3;
    const int wrow = warp * 16;

    const int bh = blockIdx.y;
    const int q0 = blockIdx.x * QT;
    const __half* Qb  = g_Qh  + ((size_t)bh*SEQ + q0) * DK;
    const __half* Kb  = g_Kh  + (size_t)bh*SEQ*DK;
    const __half* Vtb = g_Vth + (size_t)bh*DK*SEQ;
    const int b = bh >> 4, h = bh & (NHEAD - 1);

    #pragma unroll
    for (int i = 0; i < 4; i++) {
        int task = tid + i*256;            // 1024 uint4 tasks (Q: 128x64 half)
        int r = task >> 3, dq = task & 7;
        *(uint4*)&Qs[r*AP + dq*8] = *(const uint4*)(Qb + r*DK + dq*8);
    }
    #pragma unroll
    for (int i = 0; i < 2; i++) {
        int t2 = tid + i*256;              // 512 float4 tasks (bias: 2048 f32)
        *(float4*)&sbias[t2*4] = *(const float4*)&g_bias[b*SEQ + t2*4];
    }

    uint4 pk[2], pv[2];
    #pragma unroll
    for (int j = 0; j < 2; j++) {
        int task = tid + j*256;
        int r = task >> 3, dq = task & 7;
        pk[j] = *(const uint4*)(Kb  + (size_t)r*DK + dq*8);
        pv[j] = *(const uint4*)(Vtb + (size_t)r*SEQ + dq*8);
    }

    __syncthreads();

    unsigned qa[4][4];
    #pragma unroll
    for (int ks = 0; ks < 4; ks++) {
        const int kb = ks * 16;
        qa[ks][0] = *(const unsigned*)&Qs[(wrow + lr    )*AP + kb + 2*qq];
        qa[ks][1] = *(const unsigned*)&Qs[(wrow + lr + 8)*AP + kb + 2*qq];
        qa[ks][2] = *(const unsigned*)&Qs[(wrow + lr    )*AP + kb + 2*qq + 8];
        qa[ks][3] = *(const unsigned*)&Qs[(wrow + lr + 8)*AP + kb + 2*qq + 8];
    }

    float S[8][4], O[8][4];
    float mrow[2] = {-INFINITY, -INFINITY};
    float lrow[2] = {0.0f, 0.0f};
    #pragma unroll
    for (int nt = 0; nt < 8; nt++)
        #pragma unroll
        for (int e = 0; e < 4; e++) O[nt][e] = 0.0f;

    for (int t = 0; t < SEQ/64; t++) {
        __syncthreads();
        #pragma unroll
        for (int j = 0; j < 2; j++) {
            int task = tid + j*256;
            int r = task >> 3, dq = task & 7;
            *(uint4*)&Ks[r*AP + dq*8] = pk[j];
            *(uint4*)&Vt[r*AP + dq*8] = pv[j];
        }
        __syncthreads();

        {
            int tn = (t + 1 < SEQ/64) ? t + 1 : t;
            #pragma unroll
            for (int j = 0; j < 2; j++) {
                int task = tid + j*256;
                int r = task >> 3, dq = task & 7;
                pk[j] = *(const uint4*)(Kb  + (size_t)(tn*64 + r)*DK + dq*8);
                pv[j] = *(const uint4*)(Vtb + (size_t)r*SEQ + tn*64 + dq*8);
            }
        }

        // ---- S = Q K^T ----
        #pragma unroll
        for (int nt = 0; nt < 8; nt++)
            #pragma unroll
            for (int e = 0; e < 4; e++) S[nt][e] = 0.0f;
        #pragma unroll
        for (int ks = 0; ks < 4; ks++) {
            const int kb = ks * 16;
            #pragma unroll
            for (int nt = 0; nt < 8; nt++) {
                unsigned bb0 = *(const unsigned*)&Ks[(nt*8 + lr)*AP + kb + 2*qq];
                unsigned bb1 = *(const unsigned*)&Ks[(nt*8 + lr)*AP + kb + 2*qq + 8];
                mma_f16(S[nt], qa[ks][0], qa[ks][1], qa[ks][2], qa[ks][3], bb0, bb1);
            }
        }

        // ---- online softmax ----
        const float inv = 0.125f;
        float tm[2] = {-INFINITY, -INFINITY};
        #pragma unroll
        for (int nt = 0; nt < 8; nt++) {
            float bb0 = sbias[t*64 + nt*8 + 2*qq];
            float bb1 = sbias[t*64 + nt*8 + 2*qq + 1];
            S[nt][0] = S[nt][0]*inv + bb0;  S[nt][1] = S[nt][1]*inv + bb1;
            S[nt][2] = S[nt][2]*inv + bb0;  S[nt][3] = S[nt][3]*inv + bb1;
            tm[0] = fmaxf(tm[0], fmaxf(S[nt][0], S[nt][1]));
            tm[1] = fmaxf(tm[1], fmaxf(S[nt][2], S[nt][3]));
        }
        #pragma unroll
        for (int r = 0; r < 2; r++) {
            tm[r] = fmaxf(tm[r], __shfl_xor_sync(0xffffffffu, tm[r], 1));
            tm[r] = fmaxf(tm[r], __shfl_xor_sync(0xffffffffu, tm[r], 2));
        }
        float alpha[2];
        #pragma unroll
        for (int r = 0; r < 2; r++) {
            float mn = fmaxf(mrow[r], tm[r]);
            alpha[r] = __expf(mrow[r] - mn);
            mrow[r] = mn;
            float tl = 0.0f;
            #pragma unroll
            for (int nt = 0; nt < 8; nt++) {
                float p0 = __expf(S[nt][2*r + 0] - mn);
                float p1 = __expf(S[nt][2*r + 1] - mn);
                S[nt][2*r + 0] = p0;  S[nt][2*r + 1] = p1;
                tl += p0 + p1;
            }
            tl += __shfl_xor_sync(0xffffffffu, tl, 1);
            tl += __shfl_xor_sync(0xffffffffu, tl, 2);
            lrow[r] = lrow[r]*alpha[r] + tl;
            #pragma unroll
            for (int nt = 0; nt < 8; nt++) {
                O[nt][2*r + 0] *= alpha[r];
                O[nt][2*r + 1] *= alpha[r];
            }
        }

        // ---- O += P V : c-frag -> a-frag register repack (no smem round-trip) ----
        #pragma unroll
        for (int ks = 0; ks < 4; ks++) {
            unsigned a0 = pack2h(S[2*ks    ][0], S[2*ks    ][1]);
            unsigned a1 = pack2h(S[2*ks    ][2], S[2*ks    ][3]);
            unsigned a2 = pack2h(S[2*ks + 1][0], S[2*ks + 1][1]);
            unsigned a3 = pack2h(S[2*ks + 1][2], S[2*ks + 1][3]);
            const int kb = ks * 16;
            #pragma unroll
            for (int nt = 0; nt < 8; nt++) {
                unsigned bb0 = *(const unsigned*)&Vt[(nt*8 + lr)*AP + kb + 2*qq];
                unsigned bb1 = *(const unsigned*)&Vt[(nt*8 + lr)*AP + kb + 2*qq + 8];
                mma_f16(O[nt], a0, a1, a2, a3, bb0, bb1);
            }
        }
    }

    #pragma unroll
    for (int r = 0; r < 2; r++) {
        float invl = 1.0f / lrow[r];
        int qrow = q0 + wrow + lr + r*8;
        size_t base = ((size_t)b*SEQ + qrow)*DMODEL + h*DK;
        #pragma unroll
        for (int nt = 0; nt < 8; nt++) {
            float2 v;
            v.x = O[nt][2*r + 0] * invl;
            v.y = O[nt][2*r + 1] * invl;
            *(float2*)&out[base + nt*8 + 2*qq] = v;
        }
    }
}

// ---------------- launch -----------------------------------------------------
extern "C" void kernel_launch(void* const* d_in, const int* in_sizes, int n_in,
                              void* d_out, int out_size)
{
    const float* input = (const float*)d_in[0];
    const void*  mask  = d_in[1];
    const float* Wq    = (const float*)d_in[2];
    const float* bq    = (const float*)d_in[3];
    const float* Wk    = (const float*)d_in[4];
    const float* bk    = (const float*)d_in[5];
    const float* Wv    = (const float*)d_in[6];
    const float* bv    = (const float*)d_in[7];
    float* out = (float*)d_out;

    __half *qp, *kp, *vp;
    cudaGetSymbolAddress((void**)&qp, g_Qh);
    cudaGetSymbolAddress((void**)&kp, g_Kh);
    cudaGetSymbolAddress((void**)&vp, g_Vth);

    detect_mask_kernel<<<1, 256>>>((const unsigned int*)mask);
    build_bias_kernel<<<(BATCH*SEQ + 255)/256, 256>>>(mask);

    dim3 ggrid(DMODEL/128, (BATCH*SEQ)/128, 3);   // (8, 32, 3)
    qkv3_gemm_f16<<<ggrid, 256>>>(input, Wq, Wk, Wv, bq, bk, bv, qp, kp, vp);

    static int attn_smem_set = 0;
    const int smem_bytes = SEQ*(int)sizeof(float) + (QT + 64 + 64)*AP*(int)sizeof(__half);
    if (!attn_smem_set) {
        cudaFuncSetAttribute(attn_f16_kernel,
                             cudaFuncAttributeMaxDynamicSharedMemorySize,
                             smem_bytes);
        attn_smem_set = 1;
    }
    dim3 agrid(SEQ/QT, BHTOT);                    // (16, 32)
    attn_f16_kernel<<<agrid, 256, smem_bytes>>>(out);
}